// round 9
// baseline (speedup 1.0000x reference)
#include <cuda_runtime.h>

// ---------------------------------------------------------------------------
// YOLOv3 loss — SINGLE-KERNEL producer/consumer version.
// Inputs: 0:p0[B,255,13,13] 1:p1[B,255,26,26] 2:p2[B,255,52,52] (f32)
//         3:targets[B,N,5] f32  4:gt_valid[B,N] (dtype auto)  5:anchors[9,2]
// Output: scalar f32.
//
// Roles by blockIdx:
//   0                       producer: full target scatter in SMEM (bitmap
//                           dedup + hash winner), exports g_list w/ embedded
//                           winner, raises g_ready.
//   [1, 1+nDense)           dense noobj sum (independent of scatter).
//   [1+nDense, grid)        sparse correction: spin on g_ready, then
//                           grid-strided warp-per-cell.
// Reduction: per-block plain stores to g_part; done-counter; last block
// finalizes out[0] and resets g_cnt/g_ready/g_done.
// Persistent globals zero at entry and re-zeroed each call.
// ---------------------------------------------------------------------------

#define NCLS 80
#define MAXB 32
#define MAX_CELLS (MAXB * 3 * (13*13 + 26*26 + 52*52))   // 340,704
#define BM_WORDS  ((MAX_CELLS + 31) / 32)                // 10,648
#define HASH_CAP  4096                                   // >= distinct best cells (<=1920)
#define MAX_TOUCH 5760                                   // 3*3*B*N bound
#define TPB       512
#define MAX_GRID  512

__device__ int    g_cnt;                 // touched-cell count
__device__ int    g_ready;               // producer handoff flag
__device__ int    g_done;                // finished-block counter
__device__ int    g_list[MAX_TOUCH];     // geom(22b) | (winner n+1)<<22
__device__ double g_part[2 * MAX_GRID];  // per-block [loss, npos]

__device__ __forceinline__ float sp(float x) {       // fast softplus
    return fmaxf(x, 0.f) + __logf(1.f + __expf(-fabsf(x)));
}
__device__ __forceinline__ float bcef(float x, float t) { return sp(x) - x * t; }
__device__ __forceinline__ float warp_sum(float v) {
    #pragma unroll
    for (int o = 16; o; o >>= 1) v += __shfl_xor_sync(0xffffffffu, v, o);
    return v;
}
__device__ __forceinline__ unsigned int hash_cell(int cell) {
    return ((unsigned int)cell * 2654435761u) >> 20;     // 12-bit slot
}

__global__ void __launch_bounds__(TPB)
k_all(const float* __restrict__ p0,
      const float* __restrict__ p1,
      const float* __restrict__ p2,
      const float* __restrict__ targets,
      const unsigned char* __restrict__ gv,
      const float* __restrict__ anchors,
      int B, int N, int nDense, int nSparseWarps, float* out) {
    extern __shared__ int smem[];
    // SMEM layout (only block 0 uses the big arrays):
    unsigned int* bm = (unsigned int*)smem;              // BM_WORDS
    int* hk = smem + BM_WORDS;                           // HASH_CAP keys
    int* hv = hk + HASH_CAP;                             // HASH_CAP vals
    int* tl = hv + HASH_CAP;                             // MAX_TOUCH geom list

    __shared__ double sl[TPB / 32], sn[TPB / 32];
    __shared__ int    scnt, flags[2];

    int tid  = threadIdx.x;
    int lane = tid & 31, w = tid >> 5;
    int blk  = blockIdx.x;

    double dsum = 0.0, psum = 0.0;   // per-thread partials
    float  fsum = 0.f;

    if (blk == 0) {
        // ================= PRODUCER =================
        // 1. zero scratch
        for (int k = tid; k < BM_WORDS; k += TPB) bm[k] = 0u;
        for (int k = tid; k < HASH_CAP; k += TPB) { hk[k] = -1; hv[k] = 0; }
        if (tid < 2) flags[tid] = 0;
        if (tid == 0) scnt = 0;
        __syncthreads();

        // 2. classify gt_valid dtype from raw bytes
        for (int p = tid; p < B * N; p += TPB) {
            unsigned char v = gv[p];
            if (v == 0x3F) atomicOr(&flags[0], 1);
            if ((p & 3) != 0 && v != 0) atomicOr(&flags[1], 1);
        }
        __syncthreads();
        int mode = flags[0] ? 0 : (flags[1] ? 2 : 1);    // 0=f32 1=i32 2=u8

        // 3. scatter all (scale, target) items
        int items = 3 * B * N;
        for (int it = tid; it < items; it += TPB) {
            int s = it / (B * N);
            int r = it % (B * N);
            int b = r / N, n = r % N;

            bool valid;
            if (mode == 0)      valid = ((const float*)gv)[b * N + n] != 0.f;
            else if (mode == 1) valid = ((const int*)gv)[b * N + n]   != 0;
            else                valid = gv[b * N + n] != 0;
            if (!valid) continue;

            const float* tg = targets + (size_t)(b * N + n) * 5;
            float gx = tg[0], gy = tg[1], gw = tg[2], gh = tg[3];

            int H   = (s == 0) ? 13 : (s == 1) ? 26 : 52;
            int off = (s == 0) ? 0 : (s == 1) ? B * 3 * 169 : B * 3 * (169 + 676);
            int HW  = H * H;

            float ious[3];
            float best_iou = -1.f; int best = 0;
            #pragma unroll
            for (int j = 0; j < 3; j++) {
                int ai = (2 - s) * 3 + j;                // ANCHOR_MASKS
                float aw = anchors[ai * 2 + 0] * (1.f / 416.f);
                float ah = anchors[ai * 2 + 1] * (1.f / 416.f);
                float inter = fminf(gw, aw) * fminf(gh, ah);
                float uni   = gw * gh + aw * ah - inter + 1e-16f;
                float iou   = inter / uni;
                ious[j] = iou;
                if (iou > best_iou) { best_iou = iou; best = j; }
            }

            int gi = min((int)(gx * H), H - 1);
            int gj = min((int)(gy * H), H - 1);
            int pbase = (s << 20) | (b << 14) | (gj << 6) | gi;

            #pragma unroll
            for (int j = 0; j < 3; j++) {
                bool is_best = (j == best);
                if (is_best || ious[j] > 0.5f) {
                    int cell = off + (b * 3 + j) * HW + gj * H + gi;
                    // dedup via SMEM bitmap
                    unsigned int m = 1u << (cell & 31);
                    if ((atomicOr(&bm[cell >> 5], m) & m) == 0) {
                        int p2i = atomicAdd(&scnt, 1);
                        tl[p2i] = pbase | (j << 12);
                    }
                    // winner via SMEM hash (best-anchor only)
                    if (is_best) {
                        unsigned int slot = hash_cell(cell);
                        for (;;) {
                            int k = hk[slot];
                            if (k == cell) break;
                            if (k == -1) {
                                int old = atomicCAS(&hk[slot], -1, cell);
                                if (old == -1 || old == cell) break;
                            }
                            slot = (slot + 1) & (HASH_CAP - 1);
                        }
                        atomicMax(&hv[slot], n + 1);
                    }
                }
            }
        }
        __syncthreads();

        // 4. export list with embedded winner
        int cnt = scnt;
        for (int k = tid; k < cnt; k += TPB) {
            int pk = tl[k];
            int s = (pk >> 20) & 3, b = (pk >> 14) & 63;
            int a = (pk >> 12) & 3, j = (pk >> 6) & 63, i = pk & 63;
            int H   = (s == 0) ? 13 : (s == 1) ? 26 : 52;
            int off = (s == 0) ? 0 : (s == 1) ? B * 3 * 169 : B * 3 * (169 + 676);
            int cell = off + (b * 3 + a) * H * H + j * H + i;
            int win = 0;
            unsigned int slot = hash_cell(cell);
            for (;;) {
                int kk = hk[slot];
                if (kk == cell) { win = hv[slot]; break; }
                if (kk == -1) break;                     // ignore-only cell
                slot = (slot + 1) & (HASH_CAP - 1);
            }
            g_list[k] = pk | (win << 22);
        }
        __syncthreads();
        if (tid == 0) {
            g_cnt = cnt;
            __threadfence();
            atomicExch(&g_ready, 1);                     // release
        }
        // producer contributes zero partials
    } else if (blk <= nDense) {
        // ================= DENSE NOOBJ =================
        int t  = (blk - 1) * TPB + tid;
        int q1 = B * 3 * 169;
        int Q  = B * 3 * 845;
        if (t < Q) {
            float sum;
            if (t < q1) {
                int r = t / 169, qi = t - r * 169;
                size_t row = (size_t)((r / 3) * 255 + (r % 3) * 85 + 4);
                float4 v = *(const float4*)(p1 + row * 676 + qi * 4);
                sum = sp(v.x) + sp(v.y) + sp(v.z) + sp(v.w);
                sum += sp(p0[row * 169 + qi]);
            } else {
                int u = t - q1;
                int r = u / 676, qi = u - r * 676;
                size_t row = (size_t)((r / 3) * 255 + (r % 3) * 85 + 4);
                float4 v = *(const float4*)(p2 + row * 2704 + qi * 4);
                sum = sp(v.x) + sp(v.y) + sp(v.z) + sp(v.w);
            }
            fsum = 0.5f * sum;
        }
    } else {
        // ================= SPARSE CORRECTION =================
        if (tid == 0) {
            while (atomicAdd(&g_ready, 0) == 0) __nanosleep(100);
        }
        __syncthreads();
        __threadfence();                                 // acquire
        int cnt = g_cnt;
        int base_warp = (blk - 1 - nDense) * (TPB / 32) + w;

        for (int ci = base_warp; ci < cnt; ci += nSparseWarps) {
            int pk = g_list[ci];
            int s = (pk >> 20) & 3, b = (pk >> 14) & 63;
            int a = (pk >> 12) & 3, j = (pk >> 6) & 63, i = pk & 63;
            int wn = (pk >> 22) & 127;                   // winner n+1, 0=none
            int H   = (s == 0) ? 13 : (s == 1) ? 26 : 52;
            int HW  = H * H;
            const float* pred = (s == 0) ? p0 : (s == 1) ? p1 : p2;
            size_t base = ((size_t)(b * 255 + a * 85)) * HW + (size_t)j * H + i;

            float conf = pred[base + (size_t)4 * HW];
            if (wn > 0) {
                const float* tg = targets + (size_t)(b * N + (wn - 1)) * 5;
                int gcls = (int)tg[4];
                float lcls = 0.f;
                #pragma unroll
                for (int c = lane; c < NCLS; c += 32) {
                    float pc = pred[base + (size_t)(5 + c) * HW];
                    lcls += bcef(pc, (c == gcls) ? 1.f : 0.f);
                }
                lcls = warp_sum(lcls);
                if (lane == 0) {
                    float gx = tg[0], gy = tg[1], gww = tg[2], ghh = tg[3];
                    int ai = (2 - s) * 3 + a;
                    float aw = anchors[ai * 2 + 0] * (1.f / 416.f);
                    float ah = anchors[ai * 2 + 1] * (1.f / 416.f);
                    float tx = gx * H - i, ty = gy * H - j;
                    float tw = logf(gww / aw), th = logf(ghh / ah);
                    float px = pred[base];
                    float py = pred[base + (size_t)1 * HW];
                    float pw = pred[base + (size_t)2 * HW];
                    float ph = pred[base + (size_t)3 * HW];
                    float lcoord = bcef(px, tx) + bcef(py, ty)
                                 + (pw - tw) * (pw - tw) + (ph - th) * (ph - th);
                    dsum += (double)(5.0f * lcoord + sp(-conf) + lcls)
                          - 0.5 * (double)sp(conf);
                    psum += 1.0;
                }
            } else if (lane == 0) {
                dsum -= 0.5 * (double)sp(conf);          // ignore-only cell
            }
        }
    }

    // ================= BLOCK REDUCTION (all roles) =================
    double dl = dsum + (double)fsum;
    #pragma unroll
    for (int o = 16; o; o >>= 1) {
        dl   += __shfl_xor_sync(0xffffffffu, dl, o);
        psum += __shfl_xor_sync(0xffffffffu, psum, o);
    }
    if (lane == 0) { sl[w] = dl; sn[w] = psum; }
    __syncthreads();
    if (tid == 0) {
        double L = 0.0, P = 0.0;
        #pragma unroll
        for (int k = 0; k < TPB / 32; k++) { L += sl[k]; P += sn[k]; }
        g_part[2 * blk]     = L;
        g_part[2 * blk + 1] = P;
        __threadfence();
        atomicAdd(&g_done, 1);
    }
    __syncthreads();

    // ================= LAST BLOCK: FINALIZE =================
    __shared__ int last;
    if (tid == 0) last = (atomicAdd(&g_done, 0) == (int)gridDim.x) ? 1 : 0;
    __syncthreads();
    if (tid == 0 && last) {
        // re-check under serialization: only ONE block can observe the full
        // count first; use an exchange to elect exactly one finalizer.
        if (atomicExch(&g_ready, 2) != 2) { /* elected below regardless */ }
    }
    // robust single-finalizer election: the block whose atomicAdd made the
    // counter reach gridDim.x does the finalize.
    // (we detect it by re-running the increment-position check)
    if (tid == 0) {
        // Note: the thread that pushed g_done to gridDim.x is unique, but we
        // used a read above. Elect via a dedicated counter:
        ;
    }
    // --- simpler correct election: use the return value captured earlier ---
    // (re-implemented below without the races above)
}

// ===========================================================================
// K_final: tiny 1-block finalize (kept as a separate trivial launch to keep
// the election logic simple and race-free).
// ===========================================================================
__global__ void __launch_bounds__(256)
k_final(float* out, int B, int P) {
    __shared__ double sL[8], sP[8];
    int lane = threadIdx.x & 31, w = threadIdx.x >> 5;
    double L = 0.0, Pp = 0.0;
    for (int i = threadIdx.x; i < P; i += 256) {
        L  += g_part[2 * i];
        Pp += g_part[2 * i + 1];
    }
    #pragma unroll
    for (int o = 16; o; o >>= 1) {
        L  += __shfl_xor_sync(0xffffffffu, L, o);
        Pp += __shfl_xor_sync(0xffffffffu, Pp, o);
    }
    if (lane == 0) { sL[w] = L; sP[w] = Pp; }
    __syncthreads();
    if (threadIdx.x == 0) {
        double l = 0.0, n = 0.0;
        #pragma unroll
        for (int k = 0; k < 8; k++) { l += sL[k]; n += sP[k]; }
        out[0] = (float)((n > 0.0) ? l / n : l / (double)B);
        g_cnt = 0; g_ready = 0; g_done = 0;              // restore invariants
    }
}

extern "C" void kernel_launch(void* const* d_in, const int* in_sizes, int n_in,
                              void* d_out, int out_size) {
    const float* p0      = (const float*)d_in[0];
    const float* p1      = (const float*)d_in[1];
    const float* p2      = (const float*)d_in[2];
    const float* targets = (const float*)d_in[3];
    const unsigned char* gvalid = (const unsigned char*)d_in[4];
    const float* anchors = (const float*)d_in[5];
    float* out = (float*)d_out;

    int B = in_sizes[0] / (255 * 13 * 13);
    int N = in_sizes[3] / (B * 5);
    if (B > MAXB) B = MAXB;

    int nDense  = (B * 3 * 845 + TPB - 1) / TPB;         // 159 @ B=32
    int nSparse = 90;                                    // grid-strided consumers
    int nSparseWarps = nSparse * (TPB / 32);
    int grid = 1 + nDense + nSparse;                     // 250 @ B=32
    if (grid > MAX_GRID) grid = MAX_GRID;

    size_t smem_bytes = (size_t)(BM_WORDS + 2 * HASH_CAP + MAX_TOUCH) * 4;

    cudaFuncSetAttribute(k_all, cudaFuncAttributeMaxDynamicSharedMemorySize,
                         (int)smem_bytes);

    k_all  <<<grid, TPB, smem_bytes>>>(p0, p1, p2, targets, gvalid, anchors,
                                       B, N, nDense, nSparseWarps, out);
    k_final<<<1, 256>>>(out, B, grid);
}

// round 11
// speedup vs baseline: 2.0211x; 2.0211x over previous
#include <cuda_runtime.h>

// ---------------------------------------------------------------------------
// YOLOv3 loss — 2 balanced launches.
//   K1: blocks [0,nScatter) target scatter; blocks [nScatter,..) dense noobj.
//   K2: warp-per-cell sparse correction + last-block finalize (no 3rd launch).
// Inputs: 0:p0[B,255,13,13] 1:p1[B,255,26,26] 2:p2[B,255,52,52] (f32)
//         3:targets[B,N,5] f32  4:gt_valid[B,N] (dtype auto)  5:anchors[9,2]
// Output: scalar f32.
// Scratch invariants (zero at entry, restored every call):
//   g_winner/g_bits: restored inline by sparse warps (unique owner per cell)
//   g_cnt/g_done   : reset by the elected last block of K2
// Reduction: plain stores to g_part (no shared-address double atomics).
// ---------------------------------------------------------------------------

#define NCLS 80
#define MAXB 32
#define MAX_CELLS (MAXB * 3 * (13*13 + 26*26 + 52*52))   // 340,704
#define MAX_TOUCH (3 * 3 * MAXB * 32)                    // 5760
#define MAX_PART  2048
#define TPB       256

__device__ int          g_cnt;
__device__ int          g_done;
__device__ int          g_winner[MAX_CELLS];             // 0=none else n+1
__device__ unsigned int g_bits[(MAX_CELLS + 31) / 32];   // dedup bitmask
__device__ int          g_list[MAX_TOUCH];               // packed (s,b,a,j,i)
__device__ double       g_part[2 * MAX_PART];            // per-block [loss,npos]

__device__ __forceinline__ float sp(float x) {           // fast softplus
    return fmaxf(x, 0.f) + __logf(1.f + __expf(-fabsf(x)));
}
__device__ __forceinline__ float bcef(float x, float t) { return sp(x) - x * t; }
__device__ __forceinline__ float warp_sum(float v) {
    #pragma unroll
    for (int o = 16; o; o >>= 1) v += __shfl_xor_sync(0xffffffffu, v, o);
    return v;
}

// ===========================================================================
// K1: scatter (blocks < nScatter) fused with dense noobj (remaining blocks).
// Every block stores its partial pair to g_part[2*blockIdx].
// ===========================================================================
__global__ void __launch_bounds__(TPB)
k_scatter_dense(const float* __restrict__ p0,
                const float* __restrict__ p1,
                const float* __restrict__ p2,
                const float* __restrict__ targets,
                const unsigned char* __restrict__ gv,
                const float* __restrict__ anchors,
                int B, int N, int nScatter) {
    int tid = threadIdx.x, lane = tid & 31, w = tid >> 5;
    int blk = blockIdx.x;
    float fsum = 0.f;

    if (blk < nScatter) {
        // ---------------- scatter role ----------------
        __shared__ int flags[2];
        if (tid < 2) flags[tid] = 0;
        __syncthreads();
        for (int p = tid; p < B * N; p += TPB) {
            unsigned char v = gv[p];
            if (v == 0x3F) atomicOr(&flags[0], 1);
            if ((p & 3) != 0 && v != 0) atomicOr(&flags[1], 1);
        }
        __syncthreads();
        int mode = flags[0] ? 0 : (flags[1] ? 2 : 1);    // 0=f32 1=i32 2=u8

        int it = blk * TPB + tid;
        int total = 3 * B * N;
        if (it < total) {
            int s = it / (B * N);
            int r = it % (B * N);
            int b = r / N, n = r % N;

            bool valid;
            if (mode == 0)      valid = ((const float*)gv)[b * N + n] != 0.f;
            else if (mode == 1) valid = ((const int*)gv)[b * N + n]   != 0;
            else                valid = gv[b * N + n] != 0;

            if (valid) {
                const float* tg = targets + (size_t)(b * N + n) * 5;
                float gx = tg[0], gy = tg[1], gw = tg[2], gh = tg[3];

                int H   = (s == 0) ? 13 : (s == 1) ? 26 : 52;
                int off = (s == 0) ? 0 : (s == 1) ? B * 3 * 169
                                                  : B * 3 * (169 + 676);
                int HW  = H * H;

                float ious[3];
                float best_iou = -1.f; int best = 0;
                #pragma unroll
                for (int j = 0; j < 3; j++) {
                    int ai = (2 - s) * 3 + j;            // ANCHOR_MASKS
                    float aw = anchors[ai * 2 + 0] * (1.f / 416.f);
                    float ah = anchors[ai * 2 + 1] * (1.f / 416.f);
                    float inter = fminf(gw, aw) * fminf(gh, ah);
                    float uni   = gw * gh + aw * ah - inter + 1e-16f;
                    float iou   = inter / uni;
                    ious[j] = iou;
                    if (iou > best_iou) { best_iou = iou; best = j; }
                }

                int gi = min((int)(gx * H), H - 1);
                int gj = min((int)(gy * H), H - 1);
                int pbase = (s << 20) | (b << 14) | (gj << 6) | gi;

                #pragma unroll
                for (int j = 0; j < 3; j++) {
                    bool is_best = (j == best);
                    if (is_best || ious[j] > 0.5f) {
                        int cell = off + (b * 3 + j) * HW + gj * H + gi;
                        if (is_best) atomicMax(&g_winner[cell], n + 1);
                        unsigned int m = 1u << (cell & 31);
                        if ((atomicOr(&g_bits[cell >> 5], m) & m) == 0) {
                            int p = atomicAdd(&g_cnt, 1);
                            g_list[p] = pbase | (j << 12);
                        }
                    }
                }
            }
        }
    } else {
        // ---------------- dense noobj role ----------------
        int t  = (blk - nScatter) * TPB + tid;
        int q1 = B * 3 * 169;          // scale-1 quads (== scale-0 elements)
        int Q  = B * 3 * 845;
        if (t < Q) {
            float sum;
            if (t < q1) {
                int r = t / 169, qi = t - r * 169;
                size_t row = (size_t)((r / 3) * 255 + (r % 3) * 85 + 4);
                float4 v = *(const float4*)(p1 + row * 676 + qi * 4);
                sum = sp(v.x) + sp(v.y) + sp(v.z) + sp(v.w);
                sum += sp(p0[row * 169 + qi]);
            } else {
                int u = t - q1;
                int r = u / 676, qi = u - r * 676;
                size_t row = (size_t)((r / 3) * 255 + (r % 3) * 85 + 4);
                float4 v = *(const float4*)(p2 + row * 2704 + qi * 4);
                sum = sp(v.x) + sp(v.y) + sp(v.z) + sp(v.w);
            }
            fsum = 0.5f * sum;
        }
    }

    // block reduction -> plain store (scatter blocks store zeros)
    __shared__ float ws[TPB / 32];
    fsum = warp_sum(fsum);
    if (lane == 0) ws[w] = fsum;
    __syncthreads();
    if (tid == 0) {
        float Lf = 0.f;
        #pragma unroll
        for (int k = 0; k < TPB / 32; k++) Lf += ws[k];
        g_part[2 * blk]     = (double)Lf;
        g_part[2 * blk + 1] = 0.0;
    }
}

// ===========================================================================
// K2: sparse correction (warp per touched cell) + last-block finalize.
// ===========================================================================
__global__ void __launch_bounds__(TPB)
k_sparse_final(const float* __restrict__ p0,
               const float* __restrict__ p1,
               const float* __restrict__ p2,
               const float* __restrict__ targets,
               const float* __restrict__ anchors,
               int B, int N, int nPartK1, float* out) {
    int tid = threadIdx.x, lane = tid & 31, w = tid >> 5;
    int blk = blockIdx.x;
    __shared__ double sl[TPB / 32], sn[TPB / 32];
    __shared__ int is_last;

    int cnt = g_cnt;
    int gw_id = blk * (TPB / 32) + w;
    double contrib = 0.0, np = 0.0;

    if (gw_id < cnt) {
        int pk = g_list[gw_id];
        int s = (pk >> 20) & 3, b = (pk >> 14) & 63;
        int a = (pk >> 12) & 3, j = (pk >> 6) & 63, i = pk & 63;
        int H   = (s == 0) ? 13 : (s == 1) ? 26 : 52;
        int off = (s == 0) ? 0 : (s == 1) ? B * 3 * 169 : B * 3 * (169 + 676);
        int HW  = H * H;
        const float* pred = (s == 0) ? p0 : (s == 1) ? p1 : p2;
        int cell = off + (b * 3 + a) * HW + j * H + i;
        size_t base = ((size_t)(b * 255 + a * 85)) * HW + (size_t)j * H + i;

        int wn = g_winner[cell];                         // n+1, 0 = none
        float conf = pred[base + (size_t)4 * HW];

        if (wn > 0) {
            const float* tg = targets + (size_t)(b * N + (wn - 1)) * 5;
            int gcls = (int)tg[4];
            float lcls = 0.f;
            #pragma unroll
            for (int c = lane; c < NCLS; c += 32) {
                float pc = pred[base + (size_t)(5 + c) * HW];
                lcls += bcef(pc, (c == gcls) ? 1.f : 0.f);
            }
            lcls = warp_sum(lcls);
            if (lane == 0) {
                float gx = tg[0], gy = tg[1], gww = tg[2], ghh = tg[3];
                int ai = (2 - s) * 3 + a;
                float aw = anchors[ai * 2 + 0] * (1.f / 416.f);
                float ah = anchors[ai * 2 + 1] * (1.f / 416.f);
                float tx = gx * H - i, ty = gy * H - j;
                float tw = logf(gww / aw), th = logf(ghh / ah);
                float px = pred[base];
                float py = pred[base + (size_t)1 * HW];
                float pw = pred[base + (size_t)2 * HW];
                float ph = pred[base + (size_t)3 * HW];
                float lcoord = bcef(px, tx) + bcef(py, ty)
                             + (pw - tw) * (pw - tw) + (ph - th) * (ph - th);
                contrib = (double)(5.0f * lcoord + sp(-conf) + lcls)
                        - 0.5 * (double)sp(conf);        // remove dense noobj
                np = 1.0;
            }
        } else if (lane == 0) {
            contrib = -0.5 * (double)sp(conf);           // ignore-only cell
        }
        // restore scratch invariant (this warp is the unique owner)
        if (lane == 0) {
            g_winner[cell] = 0;
            atomicAnd(&g_bits[cell >> 5], ~(1u << (cell & 31)));
        }
    }

    if (lane == 0) { sl[w] = contrib; sn[w] = np; }
    if (tid == 0) is_last = 0;
    __syncthreads();
    if (tid == 0) {
        double L = 0.0, P = 0.0;
        #pragma unroll
        for (int k = 0; k < TPB / 32; k++) { L += sl[k]; P += sn[k]; }
        g_part[2 * (nPartK1 + blk)]     = L;
        g_part[2 * (nPartK1 + blk) + 1] = P;
        __threadfence();
        int prev = atomicAdd(&g_done, 1);                // captured return:
        if (prev == (int)gridDim.x - 1) is_last = 1;     // unique last block
    }
    __syncthreads();

    if (is_last) {
        // all g_part entries are visible (K1 completed before K2; K2 blocks
        // fenced before incrementing g_done)
        int P = nPartK1 + (int)gridDim.x;
        double L = 0.0, Np = 0.0;
        for (int k = tid; k < P; k += TPB) {
            L  += g_part[2 * k];
            Np += g_part[2 * k + 1];
        }
        #pragma unroll
        for (int o = 16; o; o >>= 1) {
            L  += __shfl_xor_sync(0xffffffffu, L, o);
            Np += __shfl_xor_sync(0xffffffffu, Np, o);
        }
        if (lane == 0) { sl[w] = L; sn[w] = Np; }
        __syncthreads();
        if (tid == 0) {
            double l = 0.0, n = 0.0;
            #pragma unroll
            for (int k = 0; k < TPB / 32; k++) { l += sl[k]; n += sn[k]; }
            out[0] = (float)((n > 0.0) ? l / n : l / (double)B);
            g_cnt = 0; g_done = 0;                       // restore invariants
        }
    }
}

extern "C" void kernel_launch(void* const* d_in, const int* in_sizes, int n_in,
                              void* d_out, int out_size) {
    const float* p0      = (const float*)d_in[0];
    const float* p1      = (const float*)d_in[1];
    const float* p2      = (const float*)d_in[2];
    const float* targets = (const float*)d_in[3];
    const unsigned char* gvalid = (const unsigned char*)d_in[4];
    const float* anchors = (const float*)d_in[5];
    float* out = (float*)d_out;

    int B = in_sizes[0] / (255 * 13 * 13);
    int N = in_sizes[3] / (B * 5);
    if (B > MAXB) B = MAXB;   // scratch bound (shapes fixed at B=32)

    int nScatter = (3 * B * N + TPB - 1) / TPB;          // 8 @ B=32,N=20
    int nDense   = (B * 3 * 845 + TPB - 1) / TPB;        // 317 @ B=32
    int gridK1   = nScatter + nDense;                    // 325

    int touch_max = 3 * 3 * B * N;
    if (touch_max > MAX_TOUCH) touch_max = MAX_TOUCH;
    int gridK2 = (touch_max + (TPB / 32) - 1) / (TPB / 32);   // 720 @ bound

    // g_part capacity guard (never hit at B=32: 325+720=1045 <= 2048)
    if (gridK1 + gridK2 > MAX_PART) gridK2 = MAX_PART - gridK1;

    k_scatter_dense<<<gridK1, TPB>>>(p0, p1, p2, targets, gvalid, anchors,
                                     B, N, nScatter);
    k_sparse_final <<<gridK2, TPB>>>(p0, p1, p2, targets, anchors,
                                     B, N, gridK1, out);
}